// round 15
// baseline (speedup 1.0000x reference)
#include <cuda_runtime.h>
#include <cuda_fp16.h>
#include <math.h>
#include <stdint.h>

// Problem constants
#define BB 8192
#define NN 12
#define HH 512
#define TWO_H 1024
#define VV 256
#define LN_EPS 1e-5f

// ---------------------------------------------------------------------------
// Device scratch: fp16 activations + fp16 W^T + readiness counters
// ---------------------------------------------------------------------------
__device__ __align__(1024) __half g_a[(size_t)NN * BB * TWO_H];
__device__ __align__(1024) __half g_w[(size_t)NN * VV * TWO_H];
__device__ int g_cnt[128];   // per-64-row act completion counters

// ---------------------------------------------------------------------------
// PTX helpers (cp.async, ldmatrix, mma.sync, tanh.approx, f32x2 packed math)
// ---------------------------------------------------------------------------
__device__ __forceinline__ uint32_t smem_u32(const void* p) {
    uint32_t a;
    asm("{ .reg .u64 t; cvta.to.shared.u64 t, %1; cvt.u32.u64 %0, t; }" : "=r"(a) : "l"(p));
    return a;
}
__device__ __forceinline__ void cp_async16(uint32_t dst, const void* src) {
    asm volatile("cp.async.cg.shared.global [%0], [%1], 16;" :: "r"(dst), "l"(src) : "memory");
}
#define CP_ASYNC_COMMIT() asm volatile("cp.async.commit_group;" ::: "memory")

__device__ __forceinline__ void ldsm_x4(uint32_t& r0, uint32_t& r1, uint32_t& r2, uint32_t& r3,
                                        uint32_t addr) {
    asm volatile("ldmatrix.sync.aligned.m8n8.x4.shared.b16 {%0,%1,%2,%3}, [%4];"
                 : "=r"(r0), "=r"(r1), "=r"(r2), "=r"(r3) : "r"(addr));
}
__device__ __forceinline__ void mma_f16(float* d, const uint32_t* a, const uint32_t* b) {
    asm volatile(
        "mma.sync.aligned.m16n8k16.row.col.f32.f16.f16.f32 "
        "{%0,%1,%2,%3}, {%4,%5,%6,%7}, {%8,%9}, {%0,%1,%2,%3};"
        : "+f"(d[0]), "+f"(d[1]), "+f"(d[2]), "+f"(d[3])
        : "r"(a[0]), "r"(a[1]), "r"(a[2]), "r"(a[3]), "r"(b[0]), "r"(b[1]));
}
__device__ __forceinline__ float tanh_fast(float x) {
    float t;
    asm("tanh.approx.f32 %0, %1;" : "=f"(t) : "f"(x));
    return t;
}

// ---- packed f32x2 (Blackwell, PTX ISA 8.6, base sm_100-family feature) ----
__device__ __forceinline__ uint64_t pack2(float lo, float hi) {
    uint64_t r; asm("mov.b64 %0, {%1, %2};" : "=l"(r) : "f"(lo), "f"(hi)); return r;
}
__device__ __forceinline__ void unpack2(uint64_t v, float& lo, float& hi) {
    asm("mov.b64 {%0, %1}, %2;" : "=f"(lo), "=f"(hi) : "l"(v));
}
__device__ __forceinline__ uint64_t add2(uint64_t a, uint64_t b) {
    uint64_t r; asm("add.rn.f32x2 %0, %1, %2;" : "=l"(r) : "l"(a), "l"(b)); return r;
}
__device__ __forceinline__ uint64_t mul2(uint64_t a, uint64_t b) {
    uint64_t r; asm("mul.rn.f32x2 %0, %1, %2;" : "=l"(r) : "l"(a), "l"(b)); return r;
}
__device__ __forceinline__ uint64_t fma2(uint64_t a, uint64_t b, uint64_t c) {
    uint64_t r; asm("fma.rn.f32x2 %0, %1, %2, %3;" : "=l"(r) : "l"(a), "l"(b), "l"(c)); return r;
}
// half2 word: lower elem -> low 16 bits. cvt d = {hi<-a, lo<-b}
__device__ __forceinline__ uint32_t cvt_h2(float hi, float lo) {
    uint32_t r; asm("cvt.rn.f16x2.f32 %0, %1, %2;" : "=r"(r) : "f"(hi), "f"(lo)); return r;
}

#define SWZ128(o) ((o) ^ (((o) >> 3) & 0x70))

// ---------------------------------------------------------------------------
// Kernel 1: transpose + fp16 convert pred_W (N,2H,V) -> W^T (N,V,2H).
// Block (0,0,0) also zeroes the readiness counters (every graph replay).
// ---------------------------------------------------------------------------
__global__ void __launch_bounds__(256) wconv_kernel(const float* __restrict__ pred_W)
{
    __shared__ float tile[32][33];
    const int n  = blockIdx.z;
    const int k0 = blockIdx.x * 32;
    const int v0 = blockIdx.y * 32;
    const int tx = threadIdx.x, ty = threadIdx.y;

    if (blockIdx.x == 0 && blockIdx.y == 0 && blockIdx.z == 0) {
        const int t = ty * 32 + tx;
        if (t < 128) g_cnt[t] = 0;
    }

    #pragma unroll
    for (int r = 0; r < 4; r++) {
        const int k = k0 + ty + r * 8;
        tile[ty + r * 8][tx] = pred_W[((size_t)n * TWO_H + k) * VV + v0 + tx];
    }
    __syncthreads();
    #pragma unroll
    for (int r = 0; r < 4; r++) {
        const int v = v0 + ty + r * 8;
        const float w = tile[tx][ty + r * 8];
        g_w[((size_t)n * VV + v) * TWO_H + k0 + tx] = __float2half(w);
    }
}

// ---------------------------------------------------------------------------
// Fused kernel (R12 config + 7 blocks/SM): 8192 act + 6144 gemm (64x64 tiles).
// Flag protocol: act -> threadfence+atomicAdd on g_cnt[b>>6]; gemm spins until
// g_cnt[mtile]==64. smem 32KB x 7 = 224KB; regs capped to 73 by launch bounds.
// ---------------------------------------------------------------------------
#define KCH 64
#define NCHUNK (TWO_H / KCH)            // 16
#define A_BYTES (64 * 128)              // 8KB (64 rows x 64 fp16)
#define W_BYTES (64 * 128)              // 8KB
#define STAGE_BYTES (A_BYTES + W_BYTES) // 16KB
#define FUSED_DYN_SMEM (2 * STAGE_BYTES)// 32KB -> 7 blocks/SM

#define ACT_BLOCKS 8192
#define GEMM_BLOCKS 6144                 // 128 mtiles x 4 vtiles x 12 n
#define TOTAL_BLOCKS (ACT_BLOCKS + GEMM_BLOCKS)   // 14336
#define GRP_GEMM 768                     // gemm blocks per 16-mtile group

__device__ __forceinline__ void act_path(
    char* dyn, int b,
    const float* __restrict__ input_embedding,
    const int* __restrict__ features,
    const float* __restrict__ emb_tables,
    const float* __restrict__ ln_gamma,
    const float* __restrict__ ln_beta)
{
    const int tid = threadIdx.x;
    const int i = tid * 8;               // 8 dims per thread (4 f32x2 pairs)
    const bool is_ctx = (tid < 64);
    const int warp = tid >> 5;
    const int lane = tid & 31;

    float2* sh_part = reinterpret_cast<float2*>(dyn);          // [2][4]
    int* sh_feat = reinterpret_cast<int*>(dyn + 64);           // [12]

    if (tid < NN) sh_feat[tid] = features[b * NN + tid];

    // packed running values (prefix-sum half) / ctx half
    uint64_t vp[4];
    if (is_ctx) {
        const float4 a0 = *reinterpret_cast<const float4*>(input_embedding + (size_t)b * HH + i);
        const float4 a1 = *reinterpret_cast<const float4*>(input_embedding + (size_t)b * HH + i + 4);
        vp[0] = pack2(a0.x, a0.y); vp[1] = pack2(a0.z, a0.w);
        vp[2] = pack2(a1.x, a1.y); vp[3] = pack2(a1.z, a1.w);
    } else {
        vp[0] = vp[1] = vp[2] = vp[3] = 0ull;
    }
    // packed gamma/beta
    uint64_t gp[4], bp[4];
    {
        const float4 g0 = *reinterpret_cast<const float4*>(ln_gamma + i);
        const float4 g1 = *reinterpret_cast<const float4*>(ln_gamma + i + 4);
        const float4 b0 = *reinterpret_cast<const float4*>(ln_beta + i);
        const float4 b1 = *reinterpret_cast<const float4*>(ln_beta + i + 4);
        gp[0] = pack2(g0.x, g0.y); gp[1] = pack2(g0.z, g0.w);
        gp[2] = pack2(g1.x, g1.y); gp[3] = pack2(g1.z, g1.w);
        bp[0] = pack2(b0.x, b0.y); bp[1] = pack2(b0.z, b0.w);
        bp[2] = pack2(b1.x, b1.y); bp[3] = pack2(b1.z, b1.w);
    }
    const uint64_t c1c1 = pack2(0.044715f, 0.044715f);
    const uint64_t c0c0 = pack2(0.7978845608028654f, 0.7978845608028654f);

    const float inv = 1.0f / (float)TWO_H;
    __syncthreads();   // sh_feat ready

    for (int n = 0; n < NN; n++) {
        // issue the gather early; consumed at the end of this iteration
        uint64_t ep[4] = {0ull, 0ull, 0ull, 0ull};
        if (!is_ctx) {
            const int feat = sh_feat[n];
            const float* eptr = emb_tables + ((size_t)n * VV + feat) * HH + (i - HH);
            const float4 e0 = *reinterpret_cast<const float4*>(eptr);
            const float4 e1 = *reinterpret_cast<const float4*>(eptr + 4);
            ep[0] = pack2(e0.x, e0.y); ep[1] = pack2(e0.z, e0.w);
            ep[2] = pack2(e1.x, e1.y); ep[3] = pack2(e1.z, e1.w);
        }

        // packed partial sums / sum-of-squares
        uint64_t s = 0ull, q = 0ull;
        #pragma unroll
        for (int k = 0; k < 4; k++) {
            s = add2(s, vp[k]);
            q = fma2(vp[k], vp[k], q);
        }
        float slo, shi, qlo, qhi;
        unpack2(s, slo, shi);
        unpack2(q, qlo, qhi);
        float s1 = slo + shi;
        float s2 = qlo + qhi;
        #pragma unroll
        for (int o = 16; o > 0; o >>= 1) {
            s1 += __shfl_xor_sync(0xFFFFFFFFu, s1, o);
            s2 += __shfl_xor_sync(0xFFFFFFFFu, s2, o);
        }
        const int p = n & 1;
        if (lane == 0) sh_part[p * 4 + warp] = make_float2(s1, s2);
        __syncthreads();

        float ta = 0.f, tb = 0.f;
        #pragma unroll
        for (int w = 0; w < 4; w++) {
            const float2 pr = sh_part[p * 4 + w];
            ta += pr.x; tb += pr.y;
        }
        const float mu = ta * inv;
        const float rstd = rsqrtf(tb * inv - mu * mu + LN_EPS);
        const float nc = -mu * rstd;
        const uint64_t aa = pack2(rstd, rstd);
        const uint64_t cc = pack2(nc, nc);

        uint32_t h4[4];
        #pragma unroll
        for (int k = 0; k < 4; k++) {
            uint64_t y  = fma2(vp[k], aa, cc);      // (v-mu)*rstd
            y = fma2(y, gp[k], bp[k]);              // *gamma + beta
            uint64_t y2 = mul2(y, y);               // y^2
            uint64_t t3 = fma2(mul2(y2, c1c1), y, y); // c1*y^3 + y
            uint64_t ar = mul2(t3, c0c0);           // gelu arg
            float alo, ahi, ylo, yhi;
            unpack2(ar, alo, ahi);
            unpack2(y, ylo, yhi);
            const float tlo = tanh_fast(alo);
            const float thi = tanh_fast(ahi);
            const float hlo = 0.5f * ylo;
            const float hhi = 0.5f * yhi;
            const float rlo = fmaf(hlo, tlo, hlo);
            const float rhi = fmaf(hhi, thi, hhi);
            h4[k] = cvt_h2(rhi, rlo);
            vp[k] = add2(vp[k], ep[k]);             // advance prefix sum
        }
        *reinterpret_cast<uint4*>(g_a + ((size_t)n * BB + b) * TWO_H + i) =
            make_uint4(h4[0], h4[1], h4[2], h4[3]);
    }

    // publish: all writes of this block visible before the counter bump
    __threadfence();
    __syncthreads();
    if (tid == 0) atomicAdd(&g_cnt[b >> 6], 1);
}

__device__ __forceinline__ void gemm_path(
    char* dyn, int grp, int r2,
    const float* __restrict__ pred_b,
    float* __restrict__ out)
{
    const int mtile = grp * 16 + r2 / 48;   // 0..127 (64 rows each)
    const int rem   = r2 % 48;
    const int n     = rem >> 2;             // 0..11
    const int vtile = rem & 3;              // 0..3 (64 cols each)
    const int tid = threadIdx.x;
    const int wid = tid >> 5;
    const int lid = tid & 31;
    const int warpM = wid & 1;              // 0..1 -> 32 rows
    const int warpN = wid >> 1;             // 0..1 -> 32 cols

    // wait for the 64 producer rows
    if (tid == 0) {
        while (*(volatile int*)&g_cnt[mtile] < 64) __nanosleep(128);
    }
    __syncthreads();
    __threadfence();

    const uint32_t base = smem_u32(dyn);
    const __half* A = g_a + ((size_t)n * BB + (size_t)mtile * 64) * TWO_H;
    const __half* W = g_w + ((size_t)n * VV + (size_t)vtile * 64) * TWO_H;
    const int l_seg = tid & 7;

    float acc[2][4][4];
    #pragma unroll
    for (int f = 0; f < 2; f++)
        #pragma unroll
        for (int nf = 0; nf < 4; nf++)
            #pragma unroll
            for (int j = 0; j < 4; j++) acc[f][nf][j] = 0.f;

    const int lrow = lid & 15;
    const int khalf = lid >> 4;

    #define LOAD_STAGE(c, buf) do { \
        const uint32_t sA = base + (buf) * STAGE_BYTES; \
        const uint32_t sW = sA + A_BYTES; \
        const int kofs = (c) * KCH; \
        _Pragma("unroll") \
        for (int t = 0; t < 4; t++) { \
            const int row = (t * 128 + tid) >> 3; \
            const uint32_t d = SWZ128(row * 128 + l_seg * 16); \
            cp_async16(sA + d, A + (size_t)row * TWO_H + kofs + l_seg * 8); \
            cp_async16(sW + d, W + (size_t)row * TWO_H + kofs + l_seg * 8); \
        } \
        CP_ASYNC_COMMIT(); \
    } while (0)

    LOAD_STAGE(0, 0);

    for (int c = 0; c < NCHUNK; c++) {
        if (c + 1 < NCHUNK) {
            LOAD_STAGE(c + 1, (c + 1) & 1);
            asm volatile("cp.async.wait_group 1;" ::: "memory");
        } else {
            asm volatile("cp.async.wait_group 0;" ::: "memory");
        }
        __syncthreads();

        const uint32_t sA = base + (c & 1) * STAGE_BYTES;
        const uint32_t sW = sA + A_BYTES;

        #pragma unroll
        for (int ks = 0; ks < 4; ks++) {
            uint32_t ah[2][4], bh[4][2];
            #pragma unroll
            for (int f = 0; f < 2; f++) {
                const int row = warpM * 32 + f * 16 + lrow;
                const uint32_t d = SWZ128(row * 128 + ks * 32 + khalf * 16);
                ldsm_x4(ah[f][0], ah[f][1], ah[f][2], ah[f][3], sA + d);
            }
            #pragma unroll
            for (int gB = 0; gB < 2; gB++) {
                const int row = warpN * 32 + gB * 16 + lrow;
                const uint32_t d = SWZ128(row * 128 + ks * 32 + khalf * 16);
                uint32_t t0, t1, t2, t3;
                ldsm_x4(t0, t1, t2, t3, sW + d);
                bh[gB * 2][0] = t0; bh[gB * 2 + 1][0] = t1;
                bh[gB * 2][1] = t2; bh[gB * 2 + 1][1] = t3;
            }
            #pragma unroll
            for (int f = 0; f < 2; f++)
                #pragma unroll
                for (int nf = 0; nf < 4; nf++)
                    mma_f16(acc[f][nf], ah[f], bh[nf]);
        }
        __syncthreads();
    }

    const int g  = lid >> 2;
    const int tg = lid & 3;
    float2 bias[4];
    #pragma unroll
    for (int nf = 0; nf < 4; nf++) {
        const int v = vtile * 64 + warpN * 32 + nf * 8 + tg * 2;
        bias[nf] = *reinterpret_cast<const float2*>(pred_b + n * VV + v);
    }
    #pragma unroll
    for (int f = 0; f < 2; f++) {
        const int m0 = mtile * 64 + warpM * 32 + f * 16 + g;
        #pragma unroll
        for (int nf = 0; nf < 4; nf++) {
            const int v = vtile * 64 + warpN * 32 + nf * 8 + tg * 2;
            float* o0 = out + ((size_t)m0 * NN + n) * VV + v;
            float* o1 = out + ((size_t)(m0 + 8) * NN + n) * VV + v;
            float2 r0 = make_float2(acc[f][nf][0] + bias[nf].x, acc[f][nf][1] + bias[nf].y);
            float2 r1 = make_float2(acc[f][nf][2] + bias[nf].x, acc[f][nf][3] + bias[nf].y);
            *reinterpret_cast<float2*>(o0) = r0;
            *reinterpret_cast<float2*>(o1) = r1;
        }
    }
}

__global__ void __launch_bounds__(128, 7) fused_kernel(
    const float* __restrict__ input_embedding,
    const int* __restrict__ features,
    const float* __restrict__ emb_tables,
    const float* __restrict__ ln_gamma,
    const float* __restrict__ ln_beta,
    const float* __restrict__ pred_b,
    float* __restrict__ out)
{
    extern __shared__ __align__(1024) char dynsmem[];
    const int bid = blockIdx.x;

    // Interleave map:
    //  [0,2048)                 : act rows 0..2047
    //  [2048, 2048+6*1792)      : 6 supers of [1024 act rows | gemm group s]
    //  [12800, 14336)           : gemm groups 6, 7
    int b = -1, grp = -1, r2 = -1;
    if (bid < 2048) {
        b = bid;
    } else if (bid < 2048 + 6 * (1024 + GRP_GEMM)) {
        const int j = bid - 2048;
        const int sup = j / (1024 + GRP_GEMM);
        const int r = j % (1024 + GRP_GEMM);
        if (r < 1024) b = 2048 + sup * 1024 + r;
        else { grp = sup; r2 = r - 1024; }
    } else {
        const int j = bid - (2048 + 6 * (1024 + GRP_GEMM));
        grp = 6 + j / GRP_GEMM;
        r2 = j % GRP_GEMM;
    }

    if (b >= 0) {
        act_path(dynsmem, b, input_embedding, features, emb_tables, ln_gamma, ln_beta);
    } else {
        gemm_path(dynsmem, grp, r2, pred_b, out);
    }
}

// ---------------------------------------------------------------------------
extern "C" void kernel_launch(void* const* d_in, const int* in_sizes, int n_in,
                              void* d_out, int out_size)
{
    const float* input_embedding = (const float*)d_in[0];  // (B, H)
    const int*   features        = (const int*)d_in[1];    // (B, N)
    const float* emb_tables      = (const float*)d_in[2];  // (N, V, H)
    const float* ln_gamma        = (const float*)d_in[3];  // (2H,)
    const float* ln_beta         = (const float*)d_in[4];  // (2H,)
    const float* pred_W          = (const float*)d_in[5];  // (N, 2H, V)
    const float* pred_b          = (const float*)d_in[6];  // (N, V)
    float* out = (float*)d_out;                            // (B, N, V)

    cudaFuncSetAttribute(fused_kernel,
                         cudaFuncAttributeMaxDynamicSharedMemorySize, FUSED_DYN_SMEM);

    wconv_kernel<<<dim3(TWO_H / 32, VV / 32, NN), dim3(32, 8)>>>(pred_W);
    fused_kernel<<<TOTAL_BLOCKS, 128, FUSED_DYN_SMEM>>>(
        input_embedding, features, emb_tables, ln_gamma, ln_beta, pred_b, out);
}

// round 16
// speedup vs baseline: 1.0350x; 1.0350x over previous
#include <cuda_runtime.h>
#include <cuda_fp16.h>
#include <math.h>
#include <stdint.h>

// Problem constants
#define BB 8192
#define NN 12
#define HH 512
#define TWO_H 1024
#define VV 256
#define LN_EPS 1e-5f

// ---------------------------------------------------------------------------
// Device scratch: fp16 activations + fp16 W^T + readiness counters
// ---------------------------------------------------------------------------
__device__ __align__(1024) __half g_a[(size_t)NN * BB * TWO_H];
__device__ __align__(1024) __half g_w[(size_t)NN * VV * TWO_H];
__device__ int g_cnt[128];   // per-64-row act completion counters

// ---------------------------------------------------------------------------
// PTX helpers (cp.async, ldmatrix, mma.sync, tanh.approx, f32x2 packed math)
// ---------------------------------------------------------------------------
__device__ __forceinline__ uint32_t smem_u32(const void* p) {
    uint32_t a;
    asm("{ .reg .u64 t; cvta.to.shared.u64 t, %1; cvt.u32.u64 %0, t; }" : "=r"(a) : "l"(p));
    return a;
}
__device__ __forceinline__ void cp_async16(uint32_t dst, const void* src) {
    asm volatile("cp.async.cg.shared.global [%0], [%1], 16;" :: "r"(dst), "l"(src) : "memory");
}
#define CP_ASYNC_COMMIT() asm volatile("cp.async.commit_group;" ::: "memory")

__device__ __forceinline__ void ldsm_x4(uint32_t& r0, uint32_t& r1, uint32_t& r2, uint32_t& r3,
                                        uint32_t addr) {
    asm volatile("ldmatrix.sync.aligned.m8n8.x4.shared.b16 {%0,%1,%2,%3}, [%4];"
                 : "=r"(r0), "=r"(r1), "=r"(r2), "=r"(r3) : "r"(addr));
}
__device__ __forceinline__ void mma_f16(float* d, const uint32_t* a, const uint32_t* b) {
    asm volatile(
        "mma.sync.aligned.m16n8k16.row.col.f32.f16.f16.f32 "
        "{%0,%1,%2,%3}, {%4,%5,%6,%7}, {%8,%9}, {%0,%1,%2,%3};"
        : "+f"(d[0]), "+f"(d[1]), "+f"(d[2]), "+f"(d[3])
        : "r"(a[0]), "r"(a[1]), "r"(a[2]), "r"(a[3]), "r"(b[0]), "r"(b[1]));
}
__device__ __forceinline__ float tanh_fast(float x) {
    float t;
    asm("tanh.approx.f32 %0, %1;" : "=f"(t) : "f"(x));
    return t;
}

// ---- packed f32x2 (Blackwell, PTX ISA 8.6, base sm_100-family feature) ----
__device__ __forceinline__ uint64_t pack2(float lo, float hi) {
    uint64_t r; asm("mov.b64 %0, {%1, %2};" : "=l"(r) : "f"(lo), "f"(hi)); return r;
}
__device__ __forceinline__ void unpack2(uint64_t v, float& lo, float& hi) {
    asm("mov.b64 {%0, %1}, %2;" : "=f"(lo), "=f"(hi) : "l"(v));
}
__device__ __forceinline__ uint64_t add2(uint64_t a, uint64_t b) {
    uint64_t r; asm("add.rn.f32x2 %0, %1, %2;" : "=l"(r) : "l"(a), "l"(b)); return r;
}
__device__ __forceinline__ uint64_t mul2(uint64_t a, uint64_t b) {
    uint64_t r; asm("mul.rn.f32x2 %0, %1, %2;" : "=l"(r) : "l"(a), "l"(b)); return r;
}
__device__ __forceinline__ uint64_t fma2(uint64_t a, uint64_t b, uint64_t c) {
    uint64_t r; asm("fma.rn.f32x2 %0, %1, %2, %3;" : "=l"(r) : "l"(a), "l"(b), "l"(c)); return r;
}
// half2 word: lower elem -> low 16 bits. cvt d = {hi<-a, lo<-b}
__device__ __forceinline__ uint32_t cvt_h2(float hi, float lo) {
    uint32_t r; asm("cvt.rn.f16x2.f32 %0, %1, %2;" : "=r"(r) : "f"(hi), "f"(lo)); return r;
}

#define SWZ128(o) ((o) ^ (((o) >> 3) & 0x70))

// ---------------------------------------------------------------------------
// Kernel 1: transpose + fp16 convert pred_W (N,2H,V) -> W^T (N,V,2H).
// Block (0,0,0) also zeroes the readiness counters (every graph replay).
// ---------------------------------------------------------------------------
__global__ void __launch_bounds__(256) wconv_kernel(const float* __restrict__ pred_W)
{
    __shared__ float tile[32][33];
    const int n  = blockIdx.z;
    const int k0 = blockIdx.x * 32;
    const int v0 = blockIdx.y * 32;
    const int tx = threadIdx.x, ty = threadIdx.y;

    if (blockIdx.x == 0 && blockIdx.y == 0 && blockIdx.z == 0) {
        const int t = ty * 32 + tx;
        if (t < 128) g_cnt[t] = 0;
    }

    #pragma unroll
    for (int r = 0; r < 4; r++) {
        const int k = k0 + ty + r * 8;
        tile[ty + r * 8][tx] = pred_W[((size_t)n * TWO_H + k) * VV + v0 + tx];
    }
    __syncthreads();
    #pragma unroll
    for (int r = 0; r < 4; r++) {
        const int v = v0 + ty + r * 8;
        const float w = tile[tx][ty + r * 8];
        g_w[((size_t)n * VV + v) * TWO_H + k0 + tx] = __float2half(w);
    }
}

// ---------------------------------------------------------------------------
// Fused kernel (R14 config, 6 blocks/SM): 8192 act + 6144 gemm (64x64 tiles).
// Flag protocol: act -> threadfence+atomicAdd on g_cnt[b>>6]; gemm spins until
// g_cnt[mtile]==64. GEMM loop: single __syncthreads per chunk.
// Interleave slack tightened to 1 group (head 1024 act blocks).
// ---------------------------------------------------------------------------
#define KCH 64
#define NCHUNK (TWO_H / KCH)            // 16
#define A_BYTES (64 * 128)              // 8KB (64 rows x 64 fp16)
#define W_BYTES (64 * 128)              // 8KB
#define STAGE_BYTES (A_BYTES + W_BYTES) // 16KB
#define FUSED_DYN_SMEM (2 * STAGE_BYTES)// 32KB -> 6 blocks/SM

#define ACT_BLOCKS 8192
#define GEMM_BLOCKS 6144                 // 128 mtiles x 4 vtiles x 12 n
#define TOTAL_BLOCKS (ACT_BLOCKS + GEMM_BLOCKS)   // 14336
#define GRP_GEMM 768                     // gemm blocks per 16-mtile group

__device__ __forceinline__ void act_path(
    char* dyn, int b,
    const float* __restrict__ input_embedding,
    const int* __restrict__ features,
    const float* __restrict__ emb_tables,
    const float* __restrict__ ln_gamma,
    const float* __restrict__ ln_beta)
{
    const int tid = threadIdx.x;
    const int i = tid * 8;               // 8 dims per thread (4 f32x2 pairs)
    const bool is_ctx = (tid < 64);
    const int warp = tid >> 5;
    const int lane = tid & 31;

    float2* sh_part = reinterpret_cast<float2*>(dyn);          // [2][4]
    int* sh_feat = reinterpret_cast<int*>(dyn + 64);           // [12]

    if (tid < NN) sh_feat[tid] = features[b * NN + tid];

    // packed running values (prefix-sum half) / ctx half
    uint64_t vp[4];
    if (is_ctx) {
        const float4 a0 = *reinterpret_cast<const float4*>(input_embedding + (size_t)b * HH + i);
        const float4 a1 = *reinterpret_cast<const float4*>(input_embedding + (size_t)b * HH + i + 4);
        vp[0] = pack2(a0.x, a0.y); vp[1] = pack2(a0.z, a0.w);
        vp[2] = pack2(a1.x, a1.y); vp[3] = pack2(a1.z, a1.w);
    } else {
        vp[0] = vp[1] = vp[2] = vp[3] = 0ull;
    }
    // packed gamma/beta
    uint64_t gp[4], bp[4];
    {
        const float4 g0 = *reinterpret_cast<const float4*>(ln_gamma + i);
        const float4 g1 = *reinterpret_cast<const float4*>(ln_gamma + i + 4);
        const float4 b0 = *reinterpret_cast<const float4*>(ln_beta + i);
        const float4 b1 = *reinterpret_cast<const float4*>(ln_beta + i + 4);
        gp[0] = pack2(g0.x, g0.y); gp[1] = pack2(g0.z, g0.w);
        gp[2] = pack2(g1.x, g1.y); gp[3] = pack2(g1.z, g1.w);
        bp[0] = pack2(b0.x, b0.y); bp[1] = pack2(b0.z, b0.w);
        bp[2] = pack2(b1.x, b1.y); bp[3] = pack2(b1.z, b1.w);
    }
    const uint64_t c1c1 = pack2(0.044715f, 0.044715f);
    const uint64_t c0c0 = pack2(0.7978845608028654f, 0.7978845608028654f);

    const float inv = 1.0f / (float)TWO_H;
    __syncthreads();   // sh_feat ready

    for (int n = 0; n < NN; n++) {
        // issue the gather early; consumed at the end of this iteration
        uint64_t ep[4] = {0ull, 0ull, 0ull, 0ull};
        if (!is_ctx) {
            const int feat = sh_feat[n];
            const float* eptr = emb_tables + ((size_t)n * VV + feat) * HH + (i - HH);
            const float4 e0 = *reinterpret_cast<const float4*>(eptr);
            const float4 e1 = *reinterpret_cast<const float4*>(eptr + 4);
            ep[0] = pack2(e0.x, e0.y); ep[1] = pack2(e0.z, e0.w);
            ep[2] = pack2(e1.x, e1.y); ep[3] = pack2(e1.z, e1.w);
        }

        // packed partial sums / sum-of-squares
        uint64_t s = 0ull, q = 0ull;
        #pragma unroll
        for (int k = 0; k < 4; k++) {
            s = add2(s, vp[k]);
            q = fma2(vp[k], vp[k], q);
        }
        float slo, shi, qlo, qhi;
        unpack2(s, slo, shi);
        unpack2(q, qlo, qhi);
        float s1 = slo + shi;
        float s2 = qlo + qhi;
        #pragma unroll
        for (int o = 16; o > 0; o >>= 1) {
            s1 += __shfl_xor_sync(0xFFFFFFFFu, s1, o);
            s2 += __shfl_xor_sync(0xFFFFFFFFu, s2, o);
        }
        const int p = n & 1;
        if (lane == 0) sh_part[p * 4 + warp] = make_float2(s1, s2);
        __syncthreads();

        float ta = 0.f, tb = 0.f;
        #pragma unroll
        for (int w = 0; w < 4; w++) {
            const float2 pr = sh_part[p * 4 + w];
            ta += pr.x; tb += pr.y;
        }
        const float mu = ta * inv;
        const float rstd = rsqrtf(tb * inv - mu * mu + LN_EPS);
        const float nc = -mu * rstd;
        const uint64_t aa = pack2(rstd, rstd);
        const uint64_t cc = pack2(nc, nc);

        uint32_t h4[4];
        #pragma unroll
        for (int k = 0; k < 4; k++) {
            uint64_t y  = fma2(vp[k], aa, cc);      // (v-mu)*rstd
            y = fma2(y, gp[k], bp[k]);              // *gamma + beta
            uint64_t y2 = mul2(y, y);               // y^2
            uint64_t t3 = fma2(mul2(y2, c1c1), y, y); // c1*y^3 + y
            uint64_t ar = mul2(t3, c0c0);           // gelu arg
            float alo, ahi, ylo, yhi;
            unpack2(ar, alo, ahi);
            unpack2(y, ylo, yhi);
            const float tlo = tanh_fast(alo);
            const float thi = tanh_fast(ahi);
            const float hlo = 0.5f * ylo;
            const float hhi = 0.5f * yhi;
            const float rlo = fmaf(hlo, tlo, hlo);
            const float rhi = fmaf(hhi, thi, hhi);
            h4[k] = cvt_h2(rhi, rlo);
            vp[k] = add2(vp[k], ep[k]);             // advance prefix sum
        }
        *reinterpret_cast<uint4*>(g_a + ((size_t)n * BB + b) * TWO_H + i) =
            make_uint4(h4[0], h4[1], h4[2], h4[3]);
    }

    // publish: all writes of this block visible before the counter bump
    __threadfence();
    __syncthreads();
    if (tid == 0) atomicAdd(&g_cnt[b >> 6], 1);
}

__device__ __forceinline__ void gemm_path(
    char* dyn, int grp, int r2,
    const float* __restrict__ pred_b,
    float* __restrict__ out)
{
    const int mtile = grp * 16 + r2 / 48;   // 0..127 (64 rows each)
    const int rem   = r2 % 48;
    const int n     = rem >> 2;             // 0..11
    const int vtile = rem & 3;              // 0..3 (64 cols each)
    const int tid = threadIdx.x;
    const int wid = tid >> 5;
    const int lid = tid & 31;
    const int warpM = wid & 1;              // 0..1 -> 32 rows
    const int warpN = wid >> 1;             // 0..1 -> 32 cols

    // wait for the 64 producer rows
    if (tid == 0) {
        while (*(volatile int*)&g_cnt[mtile] < 64) __nanosleep(128);
    }
    __syncthreads();
    __threadfence();

    const uint32_t base = smem_u32(dyn);
    const __half* A = g_a + ((size_t)n * BB + (size_t)mtile * 64) * TWO_H;
    const __half* W = g_w + ((size_t)n * VV + (size_t)vtile * 64) * TWO_H;
    const int l_seg = tid & 7;

    float acc[2][4][4];
    #pragma unroll
    for (int f = 0; f < 2; f++)
        #pragma unroll
        for (int nf = 0; nf < 4; nf++)
            #pragma unroll
            for (int j = 0; j < 4; j++) acc[f][nf][j] = 0.f;

    const int lrow = lid & 15;
    const int khalf = lid >> 4;

    #define LOAD_STAGE(c, buf) do { \
        const uint32_t sA = base + (buf) * STAGE_BYTES; \
        const uint32_t sW = sA + A_BYTES; \
        const int kofs = (c) * KCH; \
        _Pragma("unroll") \
        for (int t = 0; t < 4; t++) { \
            const int row = (t * 128 + tid) >> 3; \
            const uint32_t d = SWZ128(row * 128 + l_seg * 16); \
            cp_async16(sA + d, A + (size_t)row * TWO_H + kofs + l_seg * 8); \
            cp_async16(sW + d, W + (size_t)row * TWO_H + kofs + l_seg * 8); \
        } \
        CP_ASYNC_COMMIT(); \
    } while (0)

    LOAD_STAGE(0, 0);

    // Single-sync pipeline: at top of chunk c, wait for load c (the only
    // in-flight group), sync (proves all warps finished reading buffer
    // (c+1)&1 during chunk c-1), then issue load c+1 into that buffer.
    for (int c = 0; c < NCHUNK; c++) {
        asm volatile("cp.async.wait_group 0;" ::: "memory");
        __syncthreads();

        if (c + 1 < NCHUNK) {
            LOAD_STAGE(c + 1, (c + 1) & 1);
        }

        const uint32_t sA = base + (c & 1) * STAGE_BYTES;
        const uint32_t sW = sA + A_BYTES;

        #pragma unroll
        for (int ks = 0; ks < 4; ks++) {
            uint32_t ah[2][4], bh[4][2];
            #pragma unroll
            for (int f = 0; f < 2; f++) {
                const int row = warpM * 32 + f * 16 + lrow;
                const uint32_t d = SWZ128(row * 128 + ks * 32 + khalf * 16);
                ldsm_x4(ah[f][0], ah[f][1], ah[f][2], ah[f][3], sA + d);
            }
            #pragma unroll
            for (int gB = 0; gB < 2; gB++) {
                const int row = warpN * 32 + gB * 16 + lrow;
                const uint32_t d = SWZ128(row * 128 + ks * 32 + khalf * 16);
                uint32_t t0, t1, t2, t3;
                ldsm_x4(t0, t1, t2, t3, sW + d);
                bh[gB * 2][0] = t0; bh[gB * 2 + 1][0] = t1;
                bh[gB * 2][1] = t2; bh[gB * 2 + 1][1] = t3;
            }
            #pragma unroll
            for (int f = 0; f < 2; f++)
                #pragma unroll
                for (int nf = 0; nf < 4; nf++)
                    mma_f16(acc[f][nf], ah[f], bh[nf]);
        }
    }

    const int g  = lid >> 2;
    const int tg = lid & 3;
    float2 bias[4];
    #pragma unroll
    for (int nf = 0; nf < 4; nf++) {
        const int v = vtile * 64 + warpN * 32 + nf * 8 + tg * 2;
        bias[nf] = *reinterpret_cast<const float2*>(pred_b + n * VV + v);
    }
    #pragma unroll
    for (int f = 0; f < 2; f++) {
        const int m0 = mtile * 64 + warpM * 32 + f * 16 + g;
        #pragma unroll
        for (int nf = 0; nf < 4; nf++) {
            const int v = vtile * 64 + warpN * 32 + nf * 8 + tg * 2;
            float* o0 = out + ((size_t)m0 * NN + n) * VV + v;
            float* o1 = out + ((size_t)(m0 + 8) * NN + n) * VV + v;
            float2 r0 = make_float2(acc[f][nf][0] + bias[nf].x, acc[f][nf][1] + bias[nf].y);
            float2 r1 = make_float2(acc[f][nf][2] + bias[nf].x, acc[f][nf][3] + bias[nf].y);
            *reinterpret_cast<float2*>(o0) = r0;
            *reinterpret_cast<float2*>(o1) = r1;
        }
    }
}

__global__ void __launch_bounds__(128, 6) fused_kernel(
    const float* __restrict__ input_embedding,
    const int* __restrict__ features,
    const float* __restrict__ emb_tables,
    const float* __restrict__ ln_gamma,
    const float* __restrict__ ln_beta,
    const float* __restrict__ pred_b,
    float* __restrict__ out)
{
    extern __shared__ __align__(1024) char dynsmem[];
    const int bid = blockIdx.x;

    // Interleave map (slack 1 group):
    //  [0,1024)                 : act rows 0..1023
    //  [1024, 1024+7*1792)      : 7 supers of [1024 act rows | gemm group s]
    //  [13568, 14336)           : gemm group 7
    // gemm group g queued after act rows 0..(g+1)*1024-1; producer distance
    // >= 1024 blocks > 888 resident slots -> in-order dispatch guarantees
    // producers complete before a dependent gemm block is scheduled.
    int b = -1, grp = -1, r2 = -1;
    if (bid < 1024) {
        b = bid;
    } else if (bid < 1024 + 7 * (1024 + GRP_GEMM)) {
        const int j = bid - 1024;
        const int sup = j / (1024 + GRP_GEMM);
        const int r = j % (1024 + GRP_GEMM);
        if (r < 1024) b = 1024 + sup * 1024 + r;
        else { grp = sup; r2 = r - 1024; }
    } else {
        const int j = bid - (1024 + 7 * (1024 + GRP_GEMM));
        grp = 7;
        r2 = j;
    }

    if (b >= 0) {
        act_path(dynsmem, b, input_embedding, features, emb_tables, ln_gamma, ln_beta);
    } else {
        gemm_path(dynsmem, grp, r2, pred_b, out);
    }
}

// ---------------------------------------------------------------------------
extern "C" void kernel_launch(void* const* d_in, const int* in_sizes, int n_in,
                              void* d_out, int out_size)
{
    const float* input_embedding = (const float*)d_in[0];  // (B, H)
    const int*   features        = (const int*)d_in[1];    // (B, N)
    const float* emb_tables      = (const float*)d_in[2];  // (N, V, H)
    const float* ln_gamma        = (const float*)d_in[3];  // (2H,)
    const float* ln_beta         = (const float*)d_in[4];  // (2H,)
    const float* pred_W          = (const float*)d_in[5];  // (N, 2H, V)
    const float* pred_b          = (const float*)d_in[6];  // (N, V)
    float* out = (float*)d_out;                            // (B, N, V)

    cudaFuncSetAttribute(fused_kernel,
                         cudaFuncAttributeMaxDynamicSharedMemorySize, FUSED_DYN_SMEM);

    wconv_kernel<<<dim3(TWO_H / 32, VV / 32, NN), dim3(32, 8)>>>(pred_W);
    fused_kernel<<<TOTAL_BLOCKS, 128, FUSED_DYN_SMEM>>>(
        input_embedding, features, emb_tables, ln_gamma, ln_beta, pred_b, out);
}

// round 17
// speedup vs baseline: 1.0468x; 1.0114x over previous
#include <cuda_runtime.h>
#include <cuda_fp16.h>
#include <math.h>
#include <stdint.h>

// Problem constants
#define BB 8192
#define NN 12
#define HH 512
#define TWO_H 1024
#define VV 256
#define LN_EPS 1e-5f

// ---------------------------------------------------------------------------
// Device scratch: fp16 activations + fp16 W^T + readiness counters
// ---------------------------------------------------------------------------
__device__ __align__(1024) __half g_a[(size_t)NN * BB * TWO_H];
__device__ __align__(1024) __half g_w[(size_t)NN * VV * TWO_H];
__device__ int g_cnt[128];   // per-64-row act completion counters

// ---------------------------------------------------------------------------
// PTX helpers (cp.async, ldmatrix, mma.sync, tanh.approx, f32x2 packed math)
// ---------------------------------------------------------------------------
__device__ __forceinline__ uint32_t smem_u32(const void* p) {
    uint32_t a;
    asm("{ .reg .u64 t; cvta.to.shared.u64 t, %1; cvt.u32.u64 %0, t; }" : "=r"(a) : "l"(p));
    return a;
}
__device__ __forceinline__ void cp_async16(uint32_t dst, const void* src) {
    asm volatile("cp.async.cg.shared.global [%0], [%1], 16;" :: "r"(dst), "l"(src) : "memory");
}
#define CP_ASYNC_COMMIT() asm volatile("cp.async.commit_group;" ::: "memory")

__device__ __forceinline__ void ldsm_x4(uint32_t& r0, uint32_t& r1, uint32_t& r2, uint32_t& r3,
                                        uint32_t addr) {
    asm volatile("ldmatrix.sync.aligned.m8n8.x4.shared.b16 {%0,%1,%2,%3}, [%4];"
                 : "=r"(r0), "=r"(r1), "=r"(r2), "=r"(r3) : "r"(addr));
}
__device__ __forceinline__ void mma_f16(float* d, const uint32_t* a, const uint32_t* b) {
    asm volatile(
        "mma.sync.aligned.m16n8k16.row.col.f32.f16.f16.f32 "
        "{%0,%1,%2,%3}, {%4,%5,%6,%7}, {%8,%9}, {%0,%1,%2,%3};"
        : "+f"(d[0]), "+f"(d[1]), "+f"(d[2]), "+f"(d[3])
        : "r"(a[0]), "r"(a[1]), "r"(a[2]), "r"(a[3]), "r"(b[0]), "r"(b[1]));
}
__device__ __forceinline__ float tanh_fast(float x) {
    float t;
    asm("tanh.approx.f32 %0, %1;" : "=f"(t) : "f"(x));
    return t;
}

// ---- packed f32x2 (Blackwell, PTX ISA 8.6, base sm_100-family feature) ----
__device__ __forceinline__ uint64_t pack2(float lo, float hi) {
    uint64_t r; asm("mov.b64 %0, {%1, %2};" : "=l"(r) : "f"(lo), "f"(hi)); return r;
}
__device__ __forceinline__ void unpack2(uint64_t v, float& lo, float& hi) {
    asm("mov.b64 {%0, %1}, %2;" : "=f"(lo), "=f"(hi) : "l"(v));
}
__device__ __forceinline__ uint64_t add2(uint64_t a, uint64_t b) {
    uint64_t r; asm("add.rn.f32x2 %0, %1, %2;" : "=l"(r) : "l"(a), "l"(b)); return r;
}
__device__ __forceinline__ uint64_t mul2(uint64_t a, uint64_t b) {
    uint64_t r; asm("mul.rn.f32x2 %0, %1, %2;" : "=l"(r) : "l"(a), "l"(b)); return r;
}
__device__ __forceinline__ uint64_t fma2(uint64_t a, uint64_t b, uint64_t c) {
    uint64_t r; asm("fma.rn.f32x2 %0, %1, %2, %3;" : "=l"(r) : "l"(a), "l"(b), "l"(c)); return r;
}
// half2 word: lower elem -> low 16 bits. cvt d = {hi<-a, lo<-b}
__device__ __forceinline__ uint32_t cvt_h2(float hi, float lo) {
    uint32_t r; asm("cvt.rn.f16x2.f32 %0, %1, %2;" : "=r"(r) : "f"(hi), "f"(lo)); return r;
}

#define SWZ128(o) ((o) ^ (((o) >> 3) & 0x70))

// ---------------------------------------------------------------------------
// Kernel 1: transpose + fp16 convert pred_W (N,2H,V) -> W^T (N,V,2H).
// Block (0,0,0) also zeroes the readiness counters (every graph replay).
// ---------------------------------------------------------------------------
__global__ void __launch_bounds__(256) wconv_kernel(const float* __restrict__ pred_W)
{
    __shared__ float tile[32][33];
    const int n  = blockIdx.z;
    const int k0 = blockIdx.x * 32;
    const int v0 = blockIdx.y * 32;
    const int tx = threadIdx.x, ty = threadIdx.y;

    if (blockIdx.x == 0 && blockIdx.y == 0 && blockIdx.z == 0) {
        const int t = ty * 32 + tx;
        if (t < 128) g_cnt[t] = 0;
    }

    #pragma unroll
    for (int r = 0; r < 4; r++) {
        const int k = k0 + ty + r * 8;
        tile[ty + r * 8][tx] = pred_W[((size_t)n * TWO_H + k) * VV + v0 + tx];
    }
    __syncthreads();
    #pragma unroll
    for (int r = 0; r < 4; r++) {
        const int v = v0 + ty + r * 8;
        const float w = tile[tx][ty + r * 8];
        g_w[((size_t)n * VV + v) * TWO_H + k0 + tx] = __float2half(w);
    }
}

// ---------------------------------------------------------------------------
// Fused kernel (R14 config, 6 blocks/SM): 8192 act + 6144 gemm (64x64 tiles).
// Fine-grained 4:3 interleave: each super = 256 x [4 act (group s+1),
// 3 gemm (group s)] so act and gemm co-reside on every SM at all times.
// Flag protocol: act -> threadfence+atomicAdd on g_cnt[b>>6]; gemm spins until
// g_cnt[mtile]==64. Producers always strictly earlier in the queue.
// ---------------------------------------------------------------------------
#define KCH 64
#define NCHUNK (TWO_H / KCH)            // 16
#define A_BYTES (64 * 128)              // 8KB (64 rows x 64 fp16)
#define W_BYTES (64 * 128)              // 8KB
#define STAGE_BYTES (A_BYTES + W_BYTES) // 16KB
#define FUSED_DYN_SMEM (2 * STAGE_BYTES)// 32KB -> 6 blocks/SM

#define ACT_BLOCKS 8192
#define GEMM_BLOCKS 6144                 // 128 mtiles x 4 vtiles x 12 n
#define TOTAL_BLOCKS (ACT_BLOCKS + GEMM_BLOCKS)   // 14336
#define GRP_GEMM 768                     // gemm blocks per 16-mtile group
#define SUPER (1024 + GRP_GEMM)          // 1792 = 256 x [4 act + 3 gemm]

__device__ __forceinline__ void act_path(
    char* dyn, int b,
    const float* __restrict__ input_embedding,
    const int* __restrict__ features,
    const float* __restrict__ emb_tables,
    const float* __restrict__ ln_gamma,
    const float* __restrict__ ln_beta)
{
    const int tid = threadIdx.x;
    const int i = tid * 8;               // 8 dims per thread (4 f32x2 pairs)
    const bool is_ctx = (tid < 64);
    const int warp = tid >> 5;
    const int lane = tid & 31;

    float2* sh_part = reinterpret_cast<float2*>(dyn);          // [2][4]
    int* sh_feat = reinterpret_cast<int*>(dyn + 64);           // [12]

    if (tid < NN) sh_feat[tid] = features[b * NN + tid];

    // packed running values (prefix-sum half) / ctx half
    uint64_t vp[4];
    if (is_ctx) {
        const float4 a0 = *reinterpret_cast<const float4*>(input_embedding + (size_t)b * HH + i);
        const float4 a1 = *reinterpret_cast<const float4*>(input_embedding + (size_t)b * HH + i + 4);
        vp[0] = pack2(a0.x, a0.y); vp[1] = pack2(a0.z, a0.w);
        vp[2] = pack2(a1.x, a1.y); vp[3] = pack2(a1.z, a1.w);
    } else {
        vp[0] = vp[1] = vp[2] = vp[3] = 0ull;
    }
    // packed gamma/beta
    uint64_t gp[4], bp[4];
    {
        const float4 g0 = *reinterpret_cast<const float4*>(ln_gamma + i);
        const float4 g1 = *reinterpret_cast<const float4*>(ln_gamma + i + 4);
        const float4 b0 = *reinterpret_cast<const float4*>(ln_beta + i);
        const float4 b1 = *reinterpret_cast<const float4*>(ln_beta + i + 4);
        gp[0] = pack2(g0.x, g0.y); gp[1] = pack2(g0.z, g0.w);
        gp[2] = pack2(g1.x, g1.y); gp[3] = pack2(g1.z, g1.w);
        bp[0] = pack2(b0.x, b0.y); bp[1] = pack2(b0.z, b0.w);
        bp[2] = pack2(b1.x, b1.y); bp[3] = pack2(b1.z, b1.w);
    }
    const uint64_t c1c1 = pack2(0.044715f, 0.044715f);
    const uint64_t c0c0 = pack2(0.7978845608028654f, 0.7978845608028654f);

    const float inv = 1.0f / (float)TWO_H;
    __syncthreads();   // sh_feat ready

    for (int n = 0; n < NN; n++) {
        // issue the gather early; consumed at the end of this iteration
        uint64_t ep[4] = {0ull, 0ull, 0ull, 0ull};
        if (!is_ctx) {
            const int feat = sh_feat[n];
            const float* eptr = emb_tables + ((size_t)n * VV + feat) * HH + (i - HH);
            const float4 e0 = *reinterpret_cast<const float4*>(eptr);
            const float4 e1 = *reinterpret_cast<const float4*>(eptr + 4);
            ep[0] = pack2(e0.x, e0.y); ep[1] = pack2(e0.z, e0.w);
            ep[2] = pack2(e1.x, e1.y); ep[3] = pack2(e1.z, e1.w);
        }

        // packed partial sums / sum-of-squares
        uint64_t s = 0ull, q = 0ull;
        #pragma unroll
        for (int k = 0; k < 4; k++) {
            s = add2(s, vp[k]);
            q = fma2(vp[k], vp[k], q);
        }
        float slo, shi, qlo, qhi;
        unpack2(s, slo, shi);
        unpack2(q, qlo, qhi);
        float s1 = slo + shi;
        float s2 = qlo + qhi;
        #pragma unroll
        for (int o = 16; o > 0; o >>= 1) {
            s1 += __shfl_xor_sync(0xFFFFFFFFu, s1, o);
            s2 += __shfl_xor_sync(0xFFFFFFFFu, s2, o);
        }
        const int p = n & 1;
        if (lane == 0) sh_part[p * 4 + warp] = make_float2(s1, s2);
        __syncthreads();

        float ta = 0.f, tb = 0.f;
        #pragma unroll
        for (int w = 0; w < 4; w++) {
            const float2 pr = sh_part[p * 4 + w];
            ta += pr.x; tb += pr.y;
        }
        const float mu = ta * inv;
        const float rstd = rsqrtf(tb * inv - mu * mu + LN_EPS);
        const float nc = -mu * rstd;
        const uint64_t aa = pack2(rstd, rstd);
        const uint64_t cc = pack2(nc, nc);

        uint32_t h4[4];
        #pragma unroll
        for (int k = 0; k < 4; k++) {
            uint64_t y  = fma2(vp[k], aa, cc);      // (v-mu)*rstd
            y = fma2(y, gp[k], bp[k]);              // *gamma + beta
            uint64_t y2 = mul2(y, y);               // y^2
            uint64_t t3 = fma2(mul2(y2, c1c1), y, y); // c1*y^3 + y
            uint64_t ar = mul2(t3, c0c0);           // gelu arg
            float alo, ahi, ylo, yhi;
            unpack2(ar, alo, ahi);
            unpack2(y, ylo, yhi);
            const float tlo = tanh_fast(alo);
            const float thi = tanh_fast(ahi);
            const float hlo = 0.5f * ylo;
            const float hhi = 0.5f * yhi;
            const float rlo = fmaf(hlo, tlo, hlo);
            const float rhi = fmaf(hhi, thi, hhi);
            h4[k] = cvt_h2(rhi, rlo);
            vp[k] = add2(vp[k], ep[k]);             // advance prefix sum
        }
        *reinterpret_cast<uint4*>(g_a + ((size_t)n * BB + b) * TWO_H + i) =
            make_uint4(h4[0], h4[1], h4[2], h4[3]);
    }

    // publish: all writes of this block visible before the counter bump
    __threadfence();
    __syncthreads();
    if (tid == 0) atomicAdd(&g_cnt[b >> 6], 1);
}

__device__ __forceinline__ void gemm_path(
    char* dyn, int grp, int r2,
    const float* __restrict__ pred_b,
    float* __restrict__ out)
{
    const int mtile = grp * 16 + r2 / 48;   // 0..127 (64 rows each)
    const int rem   = r2 % 48;
    const int n     = rem >> 2;             // 0..11
    const int vtile = rem & 3;              // 0..3 (64 cols each)
    const int tid = threadIdx.x;
    const int wid = tid >> 5;
    const int lid = tid & 31;
    const int warpM = wid & 1;              // 0..1 -> 32 rows
    const int warpN = wid >> 1;             // 0..1 -> 32 cols

    // wait for the 64 producer rows
    if (tid == 0) {
        while (*(volatile int*)&g_cnt[mtile] < 64) __nanosleep(128);
    }
    __syncthreads();
    __threadfence();

    const uint32_t base = smem_u32(dyn);
    const __half* A = g_a + ((size_t)n * BB + (size_t)mtile * 64) * TWO_H;
    const __half* W = g_w + ((size_t)n * VV + (size_t)vtile * 64) * TWO_H;
    const int l_seg = tid & 7;

    float acc[2][4][4];
    #pragma unroll
    for (int f = 0; f < 2; f++)
        #pragma unroll
        for (int nf = 0; nf < 4; nf++)
            #pragma unroll
            for (int j = 0; j < 4; j++) acc[f][nf][j] = 0.f;

    const int lrow = lid & 15;
    const int khalf = lid >> 4;

    #define LOAD_STAGE(c, buf) do { \
        const uint32_t sA = base + (buf) * STAGE_BYTES; \
        const uint32_t sW = sA + A_BYTES; \
        const int kofs = (c) * KCH; \
        _Pragma("unroll") \
        for (int t = 0; t < 4; t++) { \
            const int row = (t * 128 + tid) >> 3; \
            const uint32_t d = SWZ128(row * 128 + l_seg * 16); \
            cp_async16(sA + d, A + (size_t)row * TWO_H + kofs + l_seg * 8); \
            cp_async16(sW + d, W + (size_t)row * TWO_H + kofs + l_seg * 8); \
        } \
        CP_ASYNC_COMMIT(); \
    } while (0)

    LOAD_STAGE(0, 0);

    for (int c = 0; c < NCHUNK; c++) {
        if (c + 1 < NCHUNK) {
            LOAD_STAGE(c + 1, (c + 1) & 1);
            asm volatile("cp.async.wait_group 1;" ::: "memory");
        } else {
            asm volatile("cp.async.wait_group 0;" ::: "memory");
        }
        __syncthreads();

        const uint32_t sA = base + (c & 1) * STAGE_BYTES;
        const uint32_t sW = sA + A_BYTES;

        #pragma unroll
        for (int ks = 0; ks < 4; ks++) {
            uint32_t ah[2][4], bh[4][2];
            #pragma unroll
            for (int f = 0; f < 2; f++) {
                const int row = warpM * 32 + f * 16 + lrow;
                const uint32_t d = SWZ128(row * 128 + ks * 32 + khalf * 16);
                ldsm_x4(ah[f][0], ah[f][1], ah[f][2], ah[f][3], sA + d);
            }
            #pragma unroll
            for (int gB = 0; gB < 2; gB++) {
                const int row = warpN * 32 + gB * 16 + lrow;
                const uint32_t d = SWZ128(row * 128 + ks * 32 + khalf * 16);
                uint32_t t0, t1, t2, t3;
                ldsm_x4(t0, t1, t2, t3, sW + d);
                bh[gB * 2][0] = t0; bh[gB * 2 + 1][0] = t1;
                bh[gB * 2][1] = t2; bh[gB * 2 + 1][1] = t3;
            }
            #pragma unroll
            for (int f = 0; f < 2; f++)
                #pragma unroll
                for (int nf = 0; nf < 4; nf++)
                    mma_f16(acc[f][nf], ah[f], bh[nf]);
        }
        __syncthreads();
    }

    const int g  = lid >> 2;
    const int tg = lid & 3;
    float2 bias[4];
    #pragma unroll
    for (int nf = 0; nf < 4; nf++) {
        const int v = vtile * 64 + warpN * 32 + nf * 8 + tg * 2;
        bias[nf] = *reinterpret_cast<const float2*>(pred_b + n * VV + v);
    }
    #pragma unroll
    for (int f = 0; f < 2; f++) {
        const int m0 = mtile * 64 + warpM * 32 + f * 16 + g;
        #pragma unroll
        for (int nf = 0; nf < 4; nf++) {
            const int v = vtile * 64 + warpN * 32 + nf * 8 + tg * 2;
            float* o0 = out + ((size_t)m0 * NN + n) * VV + v;
            float* o1 = out + ((size_t)(m0 + 8) * NN + n) * VV + v;
            float2 r0 = make_float2(acc[f][nf][0] + bias[nf].x, acc[f][nf][1] + bias[nf].y);
            float2 r1 = make_float2(acc[f][nf][2] + bias[nf].x, acc[f][nf][3] + bias[nf].y);
            *reinterpret_cast<float2*>(o0) = r0;
            *reinterpret_cast<float2*>(o1) = r1;
        }
    }
}

__global__ void __launch_bounds__(128, 6) fused_kernel(
    const float* __restrict__ input_embedding,
    const int* __restrict__ features,
    const float* __restrict__ emb_tables,
    const float* __restrict__ ln_gamma,
    const float* __restrict__ ln_beta,
    const float* __restrict__ pred_b,
    float* __restrict__ out)
{
    extern __shared__ __align__(1024) char dynsmem[];
    const int bid = blockIdx.x;

    // Fine-grained interleave:
    //  [0,1024)            : act rows 0..1023 (group 0)
    //  [1024, 1024+7*1792) : 7 supers; super s = 256 x [4 act (group s+1),
    //                        3 gemm (group s)]
    //  [13568, 14336)      : gemm group 7
    // Producers (act group s, super s-1) are strictly earlier in the queue
    // than consumers (gemm group s, super s): in-order dispatch + non-blocking
    // producers => no deadlock; consumers spin briefly at worst.
    int b = -1, grp = -1, r2 = -1;
    if (bid < 1024) {
        b = bid;
    } else if (bid < 1024 + 7 * SUPER) {
        const int j = bid - 1024;
        const int sup = j / SUPER;
        const int r = j % SUPER;
        const int rep = r / 7;
        const int pos = r % 7;
        if (pos < 4) {
            b = 1024 + sup * 1024 + rep * 4 + pos;
        } else {
            grp = sup;
            r2 = rep * 3 + (pos - 4);
        }
    } else {
        grp = 7;
        r2 = bid - (1024 + 7 * SUPER);
    }

    if (b >= 0) {
        act_path(dynsmem, b, input_embedding, features, emb_tables, ln_gamma, ln_beta);
    } else {
        gemm_path(dynsmem, grp, r2, pred_b, out);
    }
}

// ---------------------------------------------------------------------------
extern "C" void kernel_launch(void* const* d_in, const int* in_sizes, int n_in,
                              void* d_out, int out_size)
{
    const float* input_embedding = (const float*)d_in[0];  // (B, H)
    const int*   features        = (const int*)d_in[1];    // (B, N)
    const float* emb_tables      = (const float*)d_in[2];  // (N, V, H)
    const float* ln_gamma        = (const float*)d_in[3];  // (2H,)
    const float* ln_beta         = (const float*)d_in[4];  // (2H,)
    const float* pred_W          = (const float*)d_in[5];  // (N, 2H, V)
    const float* pred_b          = (const float*)d_in[6];  // (N, V)
    float* out = (float*)d_out;                            // (B, N, V)

    cudaFuncSetAttribute(fused_kernel,
                         cudaFuncAttributeMaxDynamicSharedMemorySize, FUSED_DYN_SMEM);

    wconv_kernel<<<dim3(TWO_H / 32, VV / 32, NN), dim3(32, 8)>>>(pred_W);
    fused_kernel<<<TOTAL_BLOCKS, 128, FUSED_DYN_SMEM>>>(
        input_embedding, features, emb_tables, ln_gamma, ln_beta, pred_b, out);
}